// round 1
// baseline (speedup 1.0000x reference)
#include <cuda_runtime.h>

#define B 16
#define C 512
#define ICH 256
#define NN 4096
#define S 110
#define SP 112  // S padded to multiple of 4 for float4

// Scratch (device globals are zero-initialized; pads stay 0 across replays)
__device__ float g_T[(size_t)B * C * NN];   // conv outputs: ch 0..255 = theta, 256..511 = g (134 MB)
__device__ float g_pool[B * C * S];         // SPP-pooled conv outputs
__device__ float g_K2[B * C * SP];          // K2[b,c,s] = sum_ic w_phi[ic,c] * pool_theta[b,ic,s]
__device__ float g_V2[B * C * SP];          // V2[b,c,s] = sum_ic w_mask[c,ic] * pool_g[b,ic,s]
__device__ float g_att[(size_t)B * S * NN]; // scores, then attn in place

// ---------------------------------------------------------------------------
// Kernel 1: conv1x1 of y with [w_theta; w_g]  ->  g_T[b, oc, n]
// Classic 128x128x8 fp32 SGEMM, 8x8 per thread.
// ---------------------------------------------------------------------------
__global__ __launch_bounds__(256) void conv_kernel(const float* __restrict__ y,
                                                   const float* __restrict__ w_theta,
                                                   const float* __restrict__ w_g) {
    __shared__ float As[8][128];
    __shared__ float Bs[8][128];
    const int tid = threadIdx.x;
    const int nb  = blockIdx.x * 128;
    const int ocb = blockIdx.y * 128;
    const int b   = blockIdx.z;
    const float* Wbase = (ocb < 256) ? (w_theta + (size_t)ocb * 512)
                                     : (w_g + (size_t)(ocb - 256) * 512);
    const int tx = tid & 15, ty = tid >> 4;
    const int lr = tid >> 1, lk = (tid & 1) * 4;   // A-tile loader
    const int bk = tid >> 5, bn = (tid & 31) * 4;  // B-tile loader
    const float* yb = y + (size_t)b * C * NN + nb;

    float acc[8][8];
#pragma unroll
    for (int i = 0; i < 8; i++)
#pragma unroll
        for (int j = 0; j < 8; j++) acc[i][j] = 0.f;

    for (int k0 = 0; k0 < 512; k0 += 8) {
        __syncthreads();
        float4 av = *(const float4*)(Wbase + (size_t)lr * 512 + k0 + lk);
        As[lk + 0][lr] = av.x; As[lk + 1][lr] = av.y;
        As[lk + 2][lr] = av.z; As[lk + 3][lr] = av.w;
        float4 bv = *(const float4*)(yb + (size_t)(k0 + bk) * NN + bn);
        *(float4*)&Bs[bk][bn] = bv;
        __syncthreads();
#pragma unroll
        for (int k = 0; k < 8; k++) {
            float a[8], bbv[8];
            *(float4*)(a)     = *(const float4*)&As[k][ty * 4];
            *(float4*)(a + 4) = *(const float4*)&As[k][64 + ty * 4];
            *(float4*)(bbv)     = *(const float4*)&Bs[k][tx * 4];
            *(float4*)(bbv + 4) = *(const float4*)&Bs[k][64 + tx * 4];
#pragma unroll
            for (int i = 0; i < 8; i++)
#pragma unroll
                for (int j = 0; j < 8; j++) acc[i][j] += a[i] * bbv[j];
        }
    }
#pragma unroll
    for (int i = 0; i < 8; i++) {
        int oc = ocb + ((i < 4) ? (ty * 4 + i) : (64 + ty * 4 + (i - 4)));
        float* dst = g_T + ((size_t)b * C + oc) * NN + nb;
        *(float4*)(dst + tx * 4)      = make_float4(acc[i][0], acc[i][1], acc[i][2], acc[i][3]);
        *(float4*)(dst + 64 + tx * 4) = make_float4(acc[i][4], acc[i][5], acc[i][6], acc[i][7]);
    }
}

// ---------------------------------------------------------------------------
// Kernel 2: SPP adaptive max pool (levels 1,3,6,8 -> 110 bins) per (b, ch)
// ---------------------------------------------------------------------------
__global__ __launch_bounds__(128) void pool_kernel() {
    __shared__ float row[4096];
    __shared__ float colm[18 * 64];  // 1+3+6+8 h-bin rows x 64 w-cols
    const int tid = threadIdx.x;
    const int ch = blockIdx.x;
    const int b  = blockIdx.y;
    const float* src = g_T + ((size_t)b * C + ch) * NN;
    for (int i = tid * 4; i < 4096; i += 512)
        *(float4*)&row[i] = *(const float4*)&src[i];
    __syncthreads();

    const int osz[4]    = {1, 3, 6, 8};
    const int rowoff[4] = {0, 1, 4, 10};
    const int base[5]   = {0, 1, 10, 46, 110};

    if (tid < 64) {
        const int w = tid;
        for (int lv = 0; lv < 4; lv++) {
            const int o = osz[lv];
            for (int i = 0; i < o; i++) {
                int hs = (i * 64) / o;
                int he = ((i + 1) * 64 + o - 1) / o;
                float m = -3.4e38f;
                for (int h = hs; h < he; h++) m = fmaxf(m, row[h * 64 + w]);
                colm[(rowoff[lv] + i) * 64 + w] = m;
            }
        }
    }
    __syncthreads();
    if (tid < 110) {
        int lv = 0;
        while (tid >= base[lv + 1]) lv++;
        const int o = osz[lv];
        const int ij = tid - base[lv];
        const int i = ij / o, j = ij % o;
        int ws = (j * 64) / o;
        int we = ((j + 1) * 64 + o - 1) / o;
        float m = -3.4e38f;
        for (int w = ws; w < we; w++) m = fmaxf(m, colm[(rowoff[lv] + i) * 64 + w]);
        g_pool[((size_t)b * C + ch) * S + tid] = m;
    }
}

// ---------------------------------------------------------------------------
// Kernel 3: tiny per-batch GEMMs K2 = w_phi^T * pool_theta, V2 = w_mask * pool_g
// grid: (4 ctiles, which{0=K2,1=V2}, B); block 128, thread = one c
// ---------------------------------------------------------------------------
__global__ __launch_bounds__(128) void kv_kernel(const float* __restrict__ w_phi,
                                                 const float* __restrict__ w_mask) {
    __shared__ float Ps[32 * SP];
    __shared__ float Ws[4224];  // max(32*128, 128*33)
    const int tid = threadIdx.x;
    const int cb = blockIdx.x * 128;
    const int which = blockIdx.y;
    const int b = blockIdx.z;

    float acc[SP];
#pragma unroll
    for (int s = 0; s < SP; s++) acc[s] = 0.f;

    const int chb = which ? 256 : 0;
    for (int ic0 = 0; ic0 < ICH; ic0 += 32) {
        __syncthreads();
        const float* pp = g_pool + ((size_t)b * C + chb + ic0) * S;
        for (int i = tid; i < 32 * S; i += 128)
            Ps[(i / S) * SP + (i % S)] = pp[i];
        for (int i = tid; i < 32; i += 128) { Ps[i * SP + 110] = 0.f; Ps[i * SP + 111] = 0.f; }
        if (which == 0) {
            for (int i = tid; i < 32 * 128; i += 128)
                Ws[i] = w_phi[(size_t)(ic0 + i / 128) * 512 + cb + (i % 128)];
        } else {
            for (int i = tid; i < 128 * 32; i += 128)
                Ws[(i / 32) * 33 + (i % 32)] = w_mask[(size_t)(cb + i / 32) * 256 + ic0 + (i % 32)];
        }
        __syncthreads();
        for (int icc = 0; icc < 32; icc++) {
            float wv = (which == 0) ? Ws[icc * 128 + tid] : Ws[tid * 33 + icc];
#pragma unroll
            for (int s4 = 0; s4 < 28; s4++) {
                float4 p = *(const float4*)&Ps[icc * SP + s4 * 4];
                acc[s4 * 4 + 0] += wv * p.x;
                acc[s4 * 4 + 1] += wv * p.y;
                acc[s4 * 4 + 2] += wv * p.z;
                acc[s4 * 4 + 3] += wv * p.w;
            }
        }
    }
    float* dst = (which ? g_V2 : g_K2) + ((size_t)b * C + cb + tid) * SP;
    for (int s = 0; s < S; s++) dst[s] = acc[s];
}

// ---------------------------------------------------------------------------
// Kernel 4: scores[b,s,n] = sum_c x[b,c,n] * K2[b,c,s]
// block 256: thread = one n, acc[112] in registers, K2 chunk in smem
// ---------------------------------------------------------------------------
__global__ __launch_bounds__(256) void scores_kernel(const float* __restrict__ x) {
    __shared__ float Ks[64 * SP];
    const int tid = threadIdx.x;
    const int b = blockIdx.y;
    const int n = blockIdx.x * 256 + tid;
    float acc[SP];
#pragma unroll
    for (int s = 0; s < SP; s++) acc[s] = 0.f;
    const float* xb = x + (size_t)b * C * NN + n;

    for (int c0 = 0; c0 < C; c0 += 64) {
        __syncthreads();
        const float* kp = g_K2 + ((size_t)b * C + c0) * SP;
        for (int i = tid * 4; i < 64 * SP; i += 1024)
            *(float4*)&Ks[i] = *(const float4*)&kp[i];
        __syncthreads();
#pragma unroll 2
        for (int cc = 0; cc < 64; cc++) {
            float xv = xb[(size_t)(c0 + cc) * NN];
#pragma unroll
            for (int s4 = 0; s4 < 28; s4++) {
                float4 kv = *(const float4*)&Ks[cc * SP + s4 * 4];
                acc[s4 * 4 + 0] += xv * kv.x;
                acc[s4 * 4 + 1] += xv * kv.y;
                acc[s4 * 4 + 2] += xv * kv.z;
                acc[s4 * 4 + 3] += xv * kv.w;
            }
        }
    }
    float* ap = g_att + (size_t)b * S * NN + n;
    for (int s = 0; s < S; s++) ap[(size_t)s * NN] = acc[s];
}

// ---------------------------------------------------------------------------
// Kernel 5: softmax over n (4096) per (b, s) column, in place
// ---------------------------------------------------------------------------
__global__ __launch_bounds__(256) void softmax_kernel() {
    __shared__ float buf[4096];
    __shared__ float red[256];
    const int tid = threadIdx.x;
    const int s = blockIdx.x;
    const int b = blockIdx.y;
    float* rowp = g_att + ((size_t)b * S + s) * NN;
    for (int i = tid * 4; i < 4096; i += 1024)
        *(float4*)&buf[i] = *(const float4*)&rowp[i];
    __syncthreads();
    float m = -3.4e38f;
    for (int i = tid; i < 4096; i += 256) m = fmaxf(m, buf[i]);
    red[tid] = m;
    __syncthreads();
    for (int off = 128; off > 0; off >>= 1) {
        if (tid < off) red[tid] = fmaxf(red[tid], red[tid + off]);
        __syncthreads();
    }
    m = red[0];
    __syncthreads();
    float sum = 0.f;
    for (int i = tid; i < 4096; i += 256) {
        float e = expf(buf[i] - m);
        buf[i] = e;
        sum += e;
    }
    red[tid] = sum;
    __syncthreads();
    for (int off = 128; off > 0; off >>= 1) {
        if (tid < off) red[tid] += red[tid + off];
        __syncthreads();
    }
    const float inv = 1.f / red[0];
    for (int i = tid; i < 4096; i += 256) rowp[i] = buf[i] * inv;
}

// ---------------------------------------------------------------------------
// Kernel 6: out[b,c,n] = x[b,c,n] + sum_s attn[b,s,n] * V2[b,c,s]
// thread = one n, attn column (110) in registers, V2 chunk in smem
// ---------------------------------------------------------------------------
__global__ __launch_bounds__(256) void out_kernel(const float* __restrict__ x,
                                                  float* __restrict__ out) {
    __shared__ float Vs[64 * SP];
    const int tid = threadIdx.x;
    const int b = blockIdx.y;
    const int n = blockIdx.x * 256 + tid;
    float ar[SP];
    const float* ap = g_att + (size_t)b * S * NN + n;
#pragma unroll
    for (int s = 0; s < S; s++) ar[s] = ap[(size_t)s * NN];
    ar[110] = 0.f; ar[111] = 0.f;
    const float* xb = x + (size_t)b * C * NN + n;
    float* ob = out + (size_t)b * C * NN + n;

    for (int c0 = 0; c0 < C; c0 += 64) {
        __syncthreads();
        const float* vp = g_V2 + ((size_t)b * C + c0) * SP;
        for (int i = tid * 4; i < 64 * SP; i += 1024)
            *(float4*)&Vs[i] = *(const float4*)&vp[i];
        __syncthreads();
#pragma unroll 2
        for (int cc = 0; cc < 64; cc++) {
            float a0 = xb[(size_t)(c0 + cc) * NN];
            float a1 = 0.f, a2 = 0.f, a3 = 0.f;
#pragma unroll
            for (int s4 = 0; s4 < 28; s4++) {
                float4 v = *(const float4*)&Vs[cc * SP + s4 * 4];
                a0 += v.x * ar[s4 * 4 + 0];
                a1 += v.y * ar[s4 * 4 + 1];
                a2 += v.z * ar[s4 * 4 + 2];
                a3 += v.w * ar[s4 * 4 + 3];
            }
            ob[(size_t)(c0 + cc) * NN] = ((a0 + a1) + (a2 + a3));
        }
    }
}

extern "C" void kernel_launch(void* const* d_in, const int* in_sizes, int n_in,
                              void* d_out, int out_size) {
    const float* x       = (const float*)d_in[0];
    const float* y       = (const float*)d_in[1];
    const float* w_phi   = (const float*)d_in[2];
    const float* w_theta = (const float*)d_in[3];
    const float* w_g     = (const float*)d_in[4];
    const float* w_mask  = (const float*)d_in[5];
    float* out = (float*)d_out;

    conv_kernel<<<dim3(32, 4, 16), 256>>>(y, w_theta, w_g);
    pool_kernel<<<dim3(512, 16), 128>>>();
    kv_kernel<<<dim3(4, 2, 16), 128>>>(w_phi, w_mask);
    scores_kernel<<<dim3(16, 16), 256>>>(x);
    softmax_kernel<<<dim3(110, 16), 256>>>();
    out_kernel<<<dim3(16, 16), 256>>>(x, out);
}

// round 3
// speedup vs baseline: 1.4438x; 1.4438x over previous
#include <cuda_runtime.h>

#define B 16
#define C 512
#define ICH 256
#define NN 4096
#define S 110
#define SP 128  // S padded to 128 so attention GEMMs use full 128-row tiles

// Scratch (device globals zero-initialized; pad regions are never written -> stay 0)
__device__ float g_T[(size_t)B * C * NN];    // conv outputs: ch 0..255 = theta, 256..511 = g
__device__ float g_pool[B * C * S];          // SPP-pooled conv outputs (stride S=110)
__device__ float g_K2[B * C * SP];           // K2[b,c,s] = sum_ic w_phi[ic,c] * pool_theta[b,ic,s]
__device__ float g_V2[B * C * SP];           // V2[b,c,s] = sum_ic w_mask[c,ic] * pool_g[b,ic,s]
__device__ float g_att[(size_t)B * SP * NN]; // scores, then attn in place (rows 110..127 stay 0)

// ---------------------------------------------------------------------------
// Kernel 1: conv1x1 of y with [w_theta; w_g]  ->  g_T[b, oc, n]
// 128x128x8 fp32 SGEMM, 8x8 per thread.
// ---------------------------------------------------------------------------
__global__ __launch_bounds__(256) void conv_kernel(const float* __restrict__ y,
                                                   const float* __restrict__ w_theta,
                                                   const float* __restrict__ w_g) {
    __shared__ float As[8][128];
    __shared__ float Bs[8][128];
    const int tid = threadIdx.x;
    const int nb  = blockIdx.x * 128;
    const int ocb = blockIdx.y * 128;
    const int b   = blockIdx.z;
    const float* Wbase = (ocb < 256) ? (w_theta + (size_t)ocb * 512)
                                     : (w_g + (size_t)(ocb - 256) * 512);
    const int tx = tid & 15, ty = tid >> 4;
    const int lr = tid >> 1, lk = (tid & 1) * 4;   // A-tile loader
    const int bk = tid >> 5, bn = (tid & 31) * 4;  // B-tile loader
    const float* yb = y + (size_t)b * C * NN + nb;

    float acc[8][8];
#pragma unroll
    for (int i = 0; i < 8; i++)
#pragma unroll
        for (int j = 0; j < 8; j++) acc[i][j] = 0.f;

    for (int k0 = 0; k0 < 512; k0 += 8) {
        __syncthreads();
        float4 av = *(const float4*)(Wbase + (size_t)lr * 512 + k0 + lk);
        As[lk + 0][lr] = av.x; As[lk + 1][lr] = av.y;
        As[lk + 2][lr] = av.z; As[lk + 3][lr] = av.w;
        float4 bv = *(const float4*)(yb + (size_t)(k0 + bk) * NN + bn);
        *(float4*)&Bs[bk][bn] = bv;
        __syncthreads();
#pragma unroll
        for (int k = 0; k < 8; k++) {
            float a[8], bbv[8];
            *(float4*)(a)     = *(const float4*)&As[k][ty * 4];
            *(float4*)(a + 4) = *(const float4*)&As[k][64 + ty * 4];
            *(float4*)(bbv)     = *(const float4*)&Bs[k][tx * 4];
            *(float4*)(bbv + 4) = *(const float4*)&Bs[k][64 + tx * 4];
#pragma unroll
            for (int i = 0; i < 8; i++)
#pragma unroll
                for (int j = 0; j < 8; j++) acc[i][j] += a[i] * bbv[j];
        }
    }
#pragma unroll
    for (int i = 0; i < 8; i++) {
        int oc = ocb + ((i < 4) ? (ty * 4 + i) : (64 + ty * 4 + (i - 4)));
        float* dst = g_T + ((size_t)b * C + oc) * NN + nb;
        *(float4*)(dst + tx * 4)      = make_float4(acc[i][0], acc[i][1], acc[i][2], acc[i][3]);
        *(float4*)(dst + 64 + tx * 4) = make_float4(acc[i][4], acc[i][5], acc[i][6], acc[i][7]);
    }
}

// ---------------------------------------------------------------------------
// Kernel 2: SPP adaptive max pool (levels 1,3,6,8 -> 110 bins) per (b, ch)
// ---------------------------------------------------------------------------
__global__ __launch_bounds__(128) void pool_kernel() {
    __shared__ float row[4096];
    __shared__ float colm[18 * 64];
    const int tid = threadIdx.x;
    const int ch = blockIdx.x;
    const int b  = blockIdx.y;
    const float* src = g_T + ((size_t)b * C + ch) * NN;
    for (int i = tid * 4; i < 4096; i += 512)
        *(float4*)&row[i] = *(const float4*)&src[i];
    __syncthreads();

    const int osz[4]    = {1, 3, 6, 8};
    const int rowoff[4] = {0, 1, 4, 10};
    const int base[5]   = {0, 1, 10, 46, 110};

    if (tid < 64) {
        const int w = tid;
        for (int lv = 0; lv < 4; lv++) {
            const int o = osz[lv];
            for (int i = 0; i < o; i++) {
                int hs = (i * 64) / o;
                int he = ((i + 1) * 64 + o - 1) / o;
                float m = -3.4e38f;
                for (int h = hs; h < he; h++) m = fmaxf(m, row[h * 64 + w]);
                colm[(rowoff[lv] + i) * 64 + w] = m;
            }
        }
    }
    __syncthreads();
    if (tid < 110) {
        int lv = 0;
        while (tid >= base[lv + 1]) lv++;
        const int o = osz[lv];
        const int ij = tid - base[lv];
        const int i = ij / o, j = ij % o;
        int ws = (j * 64) / o;
        int we = ((j + 1) * 64 + o - 1) / o;
        float m = -3.4e38f;
        for (int w = ws; w < we; w++) m = fmaxf(m, colm[(rowoff[lv] + i) * 64 + w]);
        g_pool[((size_t)b * C + ch) * S + tid] = m;
    }
}

// ---------------------------------------------------------------------------
// Kernel 3: tiny per-batch GEMMs K2 = w_phi^T * pool_theta, V2 = w_mask * pool_g
// grid: (4 ctiles, which{0=K2,1=V2}, B); block 128, thread = one c
// Output stride SP=128, s in [110,128) written as zero.
// ---------------------------------------------------------------------------
__global__ __launch_bounds__(128) void kv_kernel(const float* __restrict__ w_phi,
                                                 const float* __restrict__ w_mask) {
    __shared__ float Ps[32 * SP];
    __shared__ float Ws[4224];  // max(32*128, 128*33)
    const int tid = threadIdx.x;
    const int cb = blockIdx.x * 128;
    const int which = blockIdx.y;
    const int b = blockIdx.z;

    float acc[SP];
#pragma unroll
    for (int s = 0; s < SP; s++) acc[s] = 0.f;

    const int chb = which ? 256 : 0;
    for (int ic0 = 0; ic0 < ICH; ic0 += 32) {
        __syncthreads();
        const float* pp = g_pool + ((size_t)b * C + chb + ic0) * S;
        for (int i = tid; i < 32 * SP; i += 128) {
            int r = i >> 7, s = i & 127;
            Ps[i] = (s < S) ? pp[r * S + s] : 0.f;
        }
        if (which == 0) {
            for (int i = tid; i < 32 * 128; i += 128)
                Ws[i] = w_phi[(size_t)(ic0 + i / 128) * 512 + cb + (i % 128)];
        } else {
            for (int i = tid; i < 128 * 32; i += 128)
                Ws[(i / 32) * 33 + (i % 32)] = w_mask[(size_t)(cb + i / 32) * 256 + ic0 + (i % 32)];
        }
        __syncthreads();
        for (int icc = 0; icc < 32; icc++) {
            float wv = (which == 0) ? Ws[icc * 128 + tid] : Ws[tid * 33 + icc];
#pragma unroll
            for (int s4 = 0; s4 < SP / 4; s4++) {
                float4 p = *(const float4*)&Ps[icc * SP + s4 * 4];
                acc[s4 * 4 + 0] += wv * p.x;
                acc[s4 * 4 + 1] += wv * p.y;
                acc[s4 * 4 + 2] += wv * p.z;
                acc[s4 * 4 + 3] += wv * p.w;
            }
        }
    }
    float* dst = (which ? g_V2 : g_K2) + ((size_t)b * C + cb + tid) * SP;
#pragma unroll
    for (int s4 = 0; s4 < SP / 4; s4++)
        *(float4*)&dst[s4 * 4] = make_float4(acc[s4 * 4], acc[s4 * 4 + 1],
                                             acc[s4 * 4 + 2], acc[s4 * 4 + 3]);
}

// ---------------------------------------------------------------------------
// Kernel 4: scores[b,s,n] = sum_c K2[b,c,s] * x[b,c,n]
// Per-batch GEMM M=128(S pad) x N=4096 x K=512, 128x128x8 tile, 8x8/thread.
// ---------------------------------------------------------------------------
__global__ __launch_bounds__(256) void scores_kernel(const float* __restrict__ x) {
    __shared__ float As[8][128];  // [k][s]
    __shared__ float Bs[8][128];  // [k][n]
    const int tid = threadIdx.x;
    const int nb = blockIdx.x * 128;
    const int b  = blockIdx.y;
    const int tx = tid & 15, ty = tid >> 4;
    const int ak = tid >> 5, am = (tid & 31) * 4;  // loader for both tiles
    const float* xb = x + (size_t)b * C * NN + nb;
    const float* Kb = g_K2 + (size_t)b * C * SP;

    float acc[8][8];
#pragma unroll
    for (int i = 0; i < 8; i++)
#pragma unroll
        for (int j = 0; j < 8; j++) acc[i][j] = 0.f;

    for (int k0 = 0; k0 < 512; k0 += 8) {
        __syncthreads();
        *(float4*)&As[ak][am] = *(const float4*)&Kb[(size_t)(k0 + ak) * SP + am];
        *(float4*)&Bs[ak][am] = *(const float4*)&xb[(size_t)(k0 + ak) * NN + am];
        __syncthreads();
#pragma unroll
        for (int k = 0; k < 8; k++) {
            float a[8], bbv[8];
            *(float4*)(a)     = *(const float4*)&As[k][ty * 4];
            *(float4*)(a + 4) = *(const float4*)&As[k][64 + ty * 4];
            *(float4*)(bbv)     = *(const float4*)&Bs[k][tx * 4];
            *(float4*)(bbv + 4) = *(const float4*)&Bs[k][64 + tx * 4];
#pragma unroll
            for (int i = 0; i < 8; i++)
#pragma unroll
                for (int j = 0; j < 8; j++) acc[i][j] += a[i] * bbv[j];
        }
    }
#pragma unroll
    for (int i = 0; i < 8; i++) {
        int m = (i < 4) ? (ty * 4 + i) : (64 + ty * 4 + (i - 4));
        if (m < S) {
            float* dst = g_att + ((size_t)b * SP + m) * NN + nb;
            *(float4*)(dst + tx * 4)      = make_float4(acc[i][0], acc[i][1], acc[i][2], acc[i][3]);
            *(float4*)(dst + 64 + tx * 4) = make_float4(acc[i][4], acc[i][5], acc[i][6], acc[i][7]);
        }
    }
}

// ---------------------------------------------------------------------------
// Kernel 5: softmax over n (4096) per (b, s) column, in place
// ---------------------------------------------------------------------------
__global__ __launch_bounds__(256) void softmax_kernel() {
    __shared__ float buf[4096];
    __shared__ float red[256];
    const int tid = threadIdx.x;
    const int s = blockIdx.x;
    const int b = blockIdx.y;
    float* rowp = g_att + ((size_t)b * SP + s) * NN;
    for (int i = tid * 4; i < 4096; i += 1024)
        *(float4*)&buf[i] = *(const float4*)&rowp[i];
    __syncthreads();
    float m = -3.4e38f;
    for (int i = tid; i < 4096; i += 256) m = fmaxf(m, buf[i]);
    red[tid] = m;
    __syncthreads();
    for (int off = 128; off > 0; off >>= 1) {
        if (tid < off) red[tid] = fmaxf(red[tid], red[tid + off]);
        __syncthreads();
    }
    m = red[0];
    __syncthreads();
    float sum = 0.f;
    for (int i = tid; i < 4096; i += 256) {
        float e = expf(buf[i] - m);
        buf[i] = e;
        sum += e;
    }
    red[tid] = sum;
    __syncthreads();
    for (int off = 128; off > 0; off >>= 1) {
        if (tid < off) red[tid] += red[tid + off];
        __syncthreads();
    }
    const float inv = 1.f / red[0];
    for (int i = tid; i < 4096; i += 256) rowp[i] = buf[i] * inv;
}

// ---------------------------------------------------------------------------
// Kernel 6: out[b,c,n] = x[b,c,n] + sum_s V2[b,c,s] * attn[b,s,n]
// Per-batch GEMM M=512 x N=4096 x K=112 (pad rows zero), 128x128x8 tile.
// ---------------------------------------------------------------------------
__global__ __launch_bounds__(256) void out_kernel(const float* __restrict__ x,
                                                  float* __restrict__ out) {
    __shared__ float As[8][128];  // [k=s][m=c]
    __shared__ float Bs[8][128];  // [k=s][n]
    const int tid = threadIdx.x;
    const int nb = blockIdx.x * 128;
    const int cb = blockIdx.y * 128;
    const int b  = blockIdx.z;
    const int tx = tid & 15, ty = tid >> 4;
    const int lr = tid >> 1, lk = (tid & 1) * 4;   // A loader (V2: k contiguous)
    const int bk = tid >> 5, bn = (tid & 31) * 4;  // B loader
    const float* Vb = g_V2 + ((size_t)b * C + cb) * SP;
    const float* Ab = g_att + (size_t)b * SP * NN + nb;

    float acc[8][8];
#pragma unroll
    for (int i = 0; i < 8; i++)
#pragma unroll
        for (int j = 0; j < 8; j++) acc[i][j] = 0.f;

    for (int k0 = 0; k0 < 112; k0 += 8) {
        __syncthreads();
        float4 av = *(const float4*)(Vb + (size_t)lr * SP + k0 + lk);
        As[lk + 0][lr] = av.x; As[lk + 1][lr] = av.y;
        As[lk + 2][lr] = av.z; As[lk + 3][lr] = av.w;
        *(float4*)&Bs[bk][bn] = *(const float4*)(Ab + (size_t)(k0 + bk) * NN + bn);
        __syncthreads();
#pragma unroll
        for (int k = 0; k < 8; k++) {
            float a[8], bbv[8];
            *(float4*)(a)     = *(const float4*)&As[k][ty * 4];
            *(float4*)(a + 4) = *(const float4*)&As[k][64 + ty * 4];
            *(float4*)(bbv)     = *(const float4*)&Bs[k][tx * 4];
            *(float4*)(bbv + 4) = *(const float4*)&Bs[k][64 + tx * 4];
#pragma unroll
            for (int i = 0; i < 8; i++)
#pragma unroll
                for (int j = 0; j < 8; j++) acc[i][j] += a[i] * bbv[j];
        }
    }
#pragma unroll
    for (int i = 0; i < 8; i++) {
        int oc = cb + ((i < 4) ? (ty * 4 + i) : (64 + ty * 4 + (i - 4)));
        const float* xs = x + ((size_t)b * C + oc) * NN + nb;
        float* od = out + ((size_t)b * C + oc) * NN + nb;
        float4 x0 = *(const float4*)(xs + tx * 4);
        float4 x1 = *(const float4*)(xs + 64 + tx * 4);
        *(float4*)(od + tx * 4) = make_float4(acc[i][0] + x0.x, acc[i][1] + x0.y,
                                              acc[i][2] + x0.z, acc[i][3] + x0.w);
        *(float4*)(od + 64 + tx * 4) = make_float4(acc[i][4] + x1.x, acc[i][5] + x1.y,
                                                   acc[i][6] + x1.z, acc[i][7] + x1.w);
    }
}

extern "C" void kernel_launch(void* const* d_in, const int* in_sizes, int n_in,
                              void* d_out, int out_size) {
    const float* x       = (const float*)d_in[0];
    const float* y       = (const float*)d_in[1];
    const float* w_phi   = (const float*)d_in[2];
    const float* w_theta = (const float*)d_in[3];
    const float* w_g     = (const float*)d_in[4];
    const float* w_mask  = (const float*)d_in[5];
    float* out = (float*)d_out;

    conv_kernel<<<dim3(32, 4, 16), 256>>>(y, w_theta, w_g);
    pool_kernel<<<dim3(512, 16), 128>>>();
    kv_kernel<<<dim3(4, 2, 16), 128>>>(w_phi, w_mask);
    scores_kernel<<<dim3(32, 16), 256>>>(x);
    softmax_kernel<<<dim3(110, 16), 256>>>();
    out_kernel<<<dim3(32, 4, 16), 256>>>(x, out);
}

// round 7
// speedup vs baseline: 1.5148x; 1.0491x over previous
#include <cuda_runtime.h>

#define B 16
#define C 512
#define ICH 256
#define NN 4096
#define S 110
#define SP 128  // S padded to 128 so attention GEMMs use full 128-row tiles

// Scratch (device globals zero-initialized; pad regions are never written -> stay 0)
__device__ float g_T[(size_t)B * C * NN];    // conv outputs: ch 0..255 = theta, 256..511 = g
__device__ float g_pool[B * C * S];          // SPP-pooled conv outputs (stride S=110)
__device__ float g_K2[B * C * SP];           // K2[b,c,s] = sum_ic w_phi[ic,c] * pool_theta[b,ic,s]
__device__ float g_V2[B * C * SP];           // V2[b,c,s] = sum_ic w_mask[c,ic] * pool_g[b,ic,s]
__device__ float g_att[(size_t)B * SP * NN]; // scores, then attn in place (rows 110..127 stay 0)

// ---------------------------------------------------------------------------
// Kernel 1: conv1x1 of y with [w_theta; w_g]  ->  g_T[b, oc, n]
// 128x128x8 fp32 SGEMM, 8x8 per thread, double-buffered smem.
// ---------------------------------------------------------------------------
__global__ __launch_bounds__(256) void conv_kernel(const float* __restrict__ y,
                                                   const float* __restrict__ w_theta,
                                                   const float* __restrict__ w_g) {
    __shared__ float As[2][8][128];
    __shared__ float Bs[2][8][128];
    const int tid = threadIdx.x;
    const int nb  = blockIdx.x * 128;
    const int ocb = blockIdx.y * 128;
    const int b   = blockIdx.z;
    const float* Wbase = (ocb < 256) ? (w_theta + (size_t)ocb * 512)
                                     : (w_g + (size_t)(ocb - 256) * 512);
    const int tx = tid & 15, ty = tid >> 4;
    const int lr = tid >> 1, lk = (tid & 1) * 4;   // A-tile loader
    const int bk = tid >> 5, bn = (tid & 31) * 4;  // B-tile loader
    const float* yb = y + (size_t)b * C * NN + nb;

    float acc[8][8];
#pragma unroll
    for (int i = 0; i < 8; i++)
#pragma unroll
        for (int j = 0; j < 8; j++) acc[i][j] = 0.f;

    float4 aP = *(const float4*)(Wbase + (size_t)lr * 512 + lk);
    float4 bP = *(const float4*)(yb + (size_t)bk * NN + bn);
    As[0][lk + 0][lr] = aP.x; As[0][lk + 1][lr] = aP.y;
    As[0][lk + 2][lr] = aP.z; As[0][lk + 3][lr] = aP.w;
    *(float4*)&Bs[0][bk][bn] = bP;
    __syncthreads();

    int cur = 0;
    for (int k0 = 8; k0 <= 512; k0 += 8) {
        if (k0 < 512) {
            aP = *(const float4*)(Wbase + (size_t)lr * 512 + k0 + lk);
            bP = *(const float4*)(yb + (size_t)(k0 + bk) * NN + bn);
        }
#pragma unroll
        for (int k = 0; k < 8; k++) {
            float a[8], bbv[8];
            *(float4*)(a)     = *(const float4*)&As[cur][k][ty * 4];
            *(float4*)(a + 4) = *(const float4*)&As[cur][k][64 + ty * 4];
            *(float4*)(bbv)     = *(const float4*)&Bs[cur][k][tx * 4];
            *(float4*)(bbv + 4) = *(const float4*)&Bs[cur][k][64 + tx * 4];
#pragma unroll
            for (int i = 0; i < 8; i++)
#pragma unroll
                for (int j = 0; j < 8; j++) acc[i][j] += a[i] * bbv[j];
        }
        if (k0 < 512) {
            const int nx = cur ^ 1;
            As[nx][lk + 0][lr] = aP.x; As[nx][lk + 1][lr] = aP.y;
            As[nx][lk + 2][lr] = aP.z; As[nx][lk + 3][lr] = aP.w;
            *(float4*)&Bs[nx][bk][bn] = bP;
            __syncthreads();
            cur = nx;
        }
    }
#pragma unroll
    for (int i = 0; i < 8; i++) {
        int oc = ocb + ((i < 4) ? (ty * 4 + i) : (64 + ty * 4 + (i - 4)));
        float* dst = g_T + ((size_t)b * C + oc) * NN + nb;
        *(float4*)(dst + tx * 4)      = make_float4(acc[i][0], acc[i][1], acc[i][2], acc[i][3]);
        *(float4*)(dst + 64 + tx * 4) = make_float4(acc[i][4], acc[i][5], acc[i][6], acc[i][7]);
    }
}

// ---------------------------------------------------------------------------
// Kernel 2: SPP adaptive max pool (levels 1,3,6,8 -> 110 bins) per (b, ch)
// ---------------------------------------------------------------------------
__global__ __launch_bounds__(128) void pool_kernel() {
    __shared__ float row[4096];
    __shared__ float colm[18 * 64];
    const int tid = threadIdx.x;
    const int ch = blockIdx.x;
    const int b  = blockIdx.y;
    const float* src = g_T + ((size_t)b * C + ch) * NN;
    for (int i = tid * 4; i < 4096; i += 512)
        *(float4*)&row[i] = *(const float4*)&src[i];
    __syncthreads();

    const int osz[4]    = {1, 3, 6, 8};
    const int rowoff[4] = {0, 1, 4, 10};
    const int base[5]   = {0, 1, 10, 46, 110};

    if (tid < 64) {
        const int w = tid;
        for (int lv = 0; lv < 4; lv++) {
            const int o = osz[lv];
            for (int i = 0; i < o; i++) {
                int hs = (i * 64) / o;
                int he = ((i + 1) * 64 + o - 1) / o;
                float m = -3.4e38f;
                for (int h = hs; h < he; h++) m = fmaxf(m, row[h * 64 + w]);
                colm[(rowoff[lv] + i) * 64 + w] = m;
            }
        }
    }
    __syncthreads();
    if (tid < 110) {
        int lv = 0;
        while (tid >= base[lv + 1]) lv++;
        const int o = osz[lv];
        const int ij = tid - base[lv];
        const int i = ij / o, j = ij % o;
        int ws = (j * 64) / o;
        int we = ((j + 1) * 64 + o - 1) / o;
        float m = -3.4e38f;
        for (int w = ws; w < we; w++) m = fmaxf(m, colm[(rowoff[lv] + i) * 64 + w]);
        g_pool[((size_t)b * C + ch) * S + tid] = m;
    }
}

// ---------------------------------------------------------------------------
// Kernel 3: tiny per-batch GEMMs K2 = w_phi^T * pool_theta, V2 = w_mask * pool_g
// ---------------------------------------------------------------------------
__global__ __launch_bounds__(128) void kv_kernel(const float* __restrict__ w_phi,
                                                 const float* __restrict__ w_mask) {
    __shared__ float Ps[32 * SP];
    __shared__ float Ws[4224];  // max(32*128, 128*33)
    const int tid = threadIdx.x;
    const int cb = blockIdx.x * 128;
    const int which = blockIdx.y;
    const int b = blockIdx.z;

    float acc[SP];
#pragma unroll
    for (int s = 0; s < SP; s++) acc[s] = 0.f;

    const int chb = which ? 256 : 0;
    for (int ic0 = 0; ic0 < ICH; ic0 += 32) {
        __syncthreads();
        const float* pp = g_pool + ((size_t)b * C + chb + ic0) * S;
        for (int i = tid; i < 32 * SP; i += 128) {
            int r = i >> 7, s = i & 127;
            Ps[i] = (s < S) ? pp[r * S + s] : 0.f;
        }
        if (which == 0) {
            for (int i = tid; i < 32 * 128; i += 128)
                Ws[i] = w_phi[(size_t)(ic0 + i / 128) * 512 + cb + (i % 128)];
        } else {
            for (int i = tid; i < 128 * 32; i += 128)
                Ws[(i / 32) * 33 + (i % 32)] = w_mask[(size_t)(cb + i / 32) * 256 + ic0 + (i % 32)];
        }
        __syncthreads();
        for (int icc = 0; icc < 32; icc++) {
            float wv = (which == 0) ? Ws[icc * 128 + tid] : Ws[tid * 33 + icc];
#pragma unroll
            for (int s4 = 0; s4 < SP / 4; s4++) {
                float4 p = *(const float4*)&Ps[icc * SP + s4 * 4];
                acc[s4 * 4 + 0] += wv * p.x;
                acc[s4 * 4 + 1] += wv * p.y;
                acc[s4 * 4 + 2] += wv * p.z;
                acc[s4 * 4 + 3] += wv * p.w;
            }
        }
    }
    float* dst = (which ? g_V2 : g_K2) + ((size_t)b * C + cb + tid) * SP;
#pragma unroll
    for (int s4 = 0; s4 < SP / 4; s4++)
        *(float4*)&dst[s4 * 4] = make_float4(acc[s4 * 4], acc[s4 * 4 + 1],
                                             acc[s4 * 4 + 2], acc[s4 * 4 + 3]);
}

// ---------------------------------------------------------------------------
// Kernel 4: scores[b,s,n] = sum_c K2[b,c,s] * x[b,c,n]
// Per-batch GEMM M=128(S pad) x N=4096 x K=512, double-buffered.
// ---------------------------------------------------------------------------
__global__ __launch_bounds__(256) void scores_kernel(const float* __restrict__ x) {
    __shared__ float As[2][8][128];  // [k][s]
    __shared__ float Bs[2][8][128];  // [k][n]
    const int tid = threadIdx.x;
    const int nb = blockIdx.x * 128;
    const int b  = blockIdx.y;
    const int tx = tid & 15, ty = tid >> 4;
    const int ak = tid >> 5, am = (tid & 31) * 4;
    const float* xb = x + (size_t)b * C * NN + nb;
    const float* Kb = g_K2 + (size_t)b * C * SP;

    float acc[8][8];
#pragma unroll
    for (int i = 0; i < 8; i++)
#pragma unroll
        for (int j = 0; j < 8; j++) acc[i][j] = 0.f;

    float4 aP = *(const float4*)&Kb[(size_t)ak * SP + am];
    float4 bP = *(const float4*)&xb[(size_t)ak * NN + am];
    *(float4*)&As[0][ak][am] = aP;
    *(float4*)&Bs[0][ak][am] = bP;
    __syncthreads();

    int cur = 0;
    for (int k0 = 8; k0 <= 512; k0 += 8) {
        if (k0 < 512) {
            aP = *(const float4*)&Kb[(size_t)(k0 + ak) * SP + am];
            bP = *(const float4*)&xb[(size_t)(k0 + ak) * NN + am];
        }
#pragma unroll
        for (int k = 0; k < 8; k++) {
            float a[8], bbv[8];
            *(float4*)(a)     = *(const float4*)&As[cur][k][ty * 4];
            *(float4*)(a + 4) = *(const float4*)&As[cur][k][64 + ty * 4];
            *(float4*)(bbv)     = *(const float4*)&Bs[cur][k][tx * 4];
            *(float4*)(bbv + 4) = *(const float4*)&Bs[cur][k][64 + tx * 4];
#pragma unroll
            for (int i = 0; i < 8; i++)
#pragma unroll
                for (int j = 0; j < 8; j++) acc[i][j] += a[i] * bbv[j];
        }
        if (k0 < 512) {
            const int nx = cur ^ 1;
            *(float4*)&As[nx][ak][am] = aP;
            *(float4*)&Bs[nx][ak][am] = bP;
            __syncthreads();
            cur = nx;
        }
    }
#pragma unroll
    for (int i = 0; i < 8; i++) {
        int m = (i < 4) ? (ty * 4 + i) : (64 + ty * 4 + (i - 4));
        if (m < S) {
            float* dst = g_att + ((size_t)b * SP + m) * NN + nb;
            *(float4*)(dst + tx * 4)      = make_float4(acc[i][0], acc[i][1], acc[i][2], acc[i][3]);
            *(float4*)(dst + 64 + tx * 4) = make_float4(acc[i][4], acc[i][5], acc[i][6], acc[i][7]);
        }
    }
}

// ---------------------------------------------------------------------------
// Kernel 5: softmax over n (4096) per (b, s) column, in place
// ---------------------------------------------------------------------------
__global__ __launch_bounds__(256) void softmax_kernel() {
    __shared__ float buf[4096];
    __shared__ float red[256];
    const int tid = threadIdx.x;
    const int s = blockIdx.x;
    const int b = blockIdx.y;
    float* rowp = g_att + ((size_t)b * SP + s) * NN;
    for (int i = tid * 4; i < 4096; i += 1024)
        *(float4*)&buf[i] = *(const float4*)&rowp[i];
    __syncthreads();
    float m = -3.4e38f;
    for (int i = tid; i < 4096; i += 256) m = fmaxf(m, buf[i]);
    red[tid] = m;
    __syncthreads();
    for (int off = 128; off > 0; off >>= 1) {
        if (tid < off) red[tid] = fmaxf(red[tid], red[tid + off]);
        __syncthreads();
    }
    m = red[0];
    __syncthreads();
    float sum = 0.f;
    for (int i = tid; i < 4096; i += 256) {
        float e = expf(buf[i] - m);
        buf[i] = e;
        sum += e;
    }
    red[tid] = sum;
    __syncthreads();
    for (int off = 128; off > 0; off >>= 1) {
        if (tid < off) red[tid] += red[tid + off];
        __syncthreads();
    }
    const float inv = 1.f / red[0];
    for (int i = tid; i < 4096; i += 256) rowp[i] = buf[i] * inv;
}

// ---------------------------------------------------------------------------
// Kernel 6: out[b,c,n] = x[b,c,n] + sum_s V2[b,c,s] * attn[b,s,n]
// Per-batch GEMM M=512 x N=4096 x K=112 (pad rows zero), double-buffered.
// ---------------------------------------------------------------------------
__global__ __launch_bounds__(256) void out_kernel(const float* __restrict__ x,
                                                  float* __restrict__ out) {
    __shared__ float As[2][8][128];  // [k=s][m=c]
    __shared__ float Bs[2][8][128];  // [k=s][n]
    const int tid = threadIdx.x;
    const int nb = blockIdx.x * 128;
    const int cb = blockIdx.y * 128;
    const int b  = blockIdx.z;
    const int tx = tid & 15, ty = tid >> 4;
    const int lr = tid >> 1, lk = (tid & 1) * 4;   // A loader (V2: k contiguous)
    const int bk = tid >> 5, bn = (tid & 31) * 4;  // B loader
    const float* Vb = g_V2 + ((size_t)b * C + cb) * SP;
    const float* Ab = g_att + (size_t)b * SP * NN + nb;

    float acc[8][8];
#pragma unroll
    for (int i = 0; i < 8; i++)
#pragma unroll
        for (int j = 0; j < 8; j++) acc[i][j] = 0.f;

    float4 aP = *(const float4*)(Vb + (size_t)lr * SP + lk);
    float4 bP = *(const float4*)(Ab + (size_t)bk * NN + bn);
    As[0][lk + 0][lr] = aP.x; As[0][lk + 1][lr] = aP.y;
    As[0][lk + 2][lr] = aP.z; As[0][lk + 3][lr] = aP.w;
    *(float4*)&Bs[0][bk][bn] = bP;
    __syncthreads();

    int cur = 0;
    for (int k0 = 8; k0 <= 112; k0 += 8) {
        if (k0 < 112) {
            aP = *(const float4*)(Vb + (size_t)lr * SP + k0 + lk);
            bP = *(const float4*)(Ab + (size_t)(k0 + bk) * NN + bn);
        }
#pragma unroll
        for (int k = 0; k < 8; k++) {
            float a[8], bbv[8];
            *(float4*)(a)     = *(const float4*)&As[cur][k][ty * 4];
            *(float4*)(a + 4) = *(const float4*)&As[cur][k][64 + ty * 4];
            *(float4*)(bbv)     = *(const float4*)&Bs[cur][k][tx * 4];
            *(float4*)(bbv + 4) = *(const float4*)&Bs[cur][k][64 + tx * 4];
#pragma unroll
            for (int i = 0; i < 8; i++)
#pragma unroll
                for (int j = 0; j < 8; j++) acc[i][j] += a[i] * bbv[j];
        }
        if (k0 < 112) {
            const int nx = cur ^ 1;
            As[nx][lk + 0][lr] = aP.x; As[nx][lk + 1][lr] = aP.y;
            As[nx][lk + 2][lr] = aP.z; As[nx][lk + 3][lr] = aP.w;
            *(float4*)&Bs[nx][bk][bn] = bP;
            __syncthreads();
            cur = nx;
        }
    }
#pragma unroll
    for (int i = 0; i < 8; i++) {
        int oc = cb + ((i < 4) ? (ty * 4 + i) : (64 + ty * 4 + (i - 4)));
        const float* xs = x + ((size_t)b * C + oc) * NN + nb;
        float* od = out + ((size_t)b * C + oc) * NN + nb;
        float4 x0 = *(const float4*)(xs + tx * 4);
        float4 x1 = *(const float4*)(xs + 64 + tx * 4);
        *(float4*)(od + tx * 4) = make_float4(acc[i][0] + x0.x, acc[i][1] + x0.y,
                                              acc[i][2] + x0.z, acc[i][3] + x0.w);
        *(float4*)(od + 64 + tx * 4) = make_float4(acc[i][4] + x1.x, acc[i][5] + x1.y,
                                                   acc[i][6] + x1.z, acc[i][7] + x1.w);
    }
}

extern "C" void kernel_launch(void* const* d_in, const int* in_sizes, int n_in,
                              void* d_out, int out_size) {
    const float* x       = (const float*)d_in[0];
    const float* y       = (const float*)d_in[1];
    const float* w_phi   = (const float*)d_in[2];
    const float* w_theta = (const float*)d_in[3];
    const float* w_g     = (const float*)d_in[4];
    const float* w_mask  = (const float*)d_in[5];
    float* out = (float*)d_out;

    conv_kernel<<<dim3(32, 4, 16), 256>>>(y, w_theta, w_g);
    pool_kernel<<<dim3(512, 16), 128>>>();
    kv_kernel<<<dim3(4, 2, 16), 128>>>(w_phi, w_mask);
    scores_kernel<<<dim3(32, 16), 256>>>(x);
    softmax_kernel<<<dim3(110, 16), 256>>>();
    out_kernel<<<dim3(32, 4, 16), 256>>>(x, out);
}